// round 1
// baseline (speedup 1.0000x reference)
#include <cuda_runtime.h>
#include <cstdint>

// Problem constants
#define T_TOK 4096
#define E_DIM 1024
#define DFF   4096
#define BB    4
#define NSTEP 128   // T / STRIDE

// ---------------- scratch (device globals; no allocations allowed) ----------------
__device__ float g_M[64 * 64];                 // w_fft2 @ w_fft1  (64x64)
__device__ float g_carry[BB * 64 * E_DIM];     // proc from previous step
__device__ float g_cn[BB * 64 * E_DIM];        // LN1 output
__device__ float g_res2[BB * 64 * E_DIM];      // fft + chunk
__device__ float g_cn2[BB * 64 * E_DIM];       // LN2 output
__device__ float g_f[BB * 64 * DFF];           // sin(gate)*val
__device__ float g_part[4 * BB * 64 * E_DIM];  // split-K partials for down GEMM

// ---------------- helpers ----------------
__device__ __forceinline__ uint32_t f2tf(float f) {
    uint32_t r;
    asm("cvt.rna.tf32.f32 %0, %1;" : "=r"(r) : "f"(f));
    return r;
}

__device__ __forceinline__ void mma8(float4& d, const uint32_t* a, const uint32_t* b) {
    asm volatile(
        "mma.sync.aligned.m16n8k8.row.col.f32.tf32.tf32.f32 "
        "{%0,%1,%2,%3},{%4,%5,%6,%7},{%8,%9},{%0,%1,%2,%3};\n"
        : "+f"(d.x), "+f"(d.y), "+f"(d.z), "+f"(d.w)
        : "r"(a[0]), "r"(a[1]), "r"(a[2]), "r"(a[3]), "r"(b[0]), "r"(b[1]));
}

// ---------------- init kernels (run once per launch, deterministic) ----------------
// M[t][s] = sum_{u<48} w_fft2[t][u] * w_fft1[u][s]
__global__ void initM_kernel(const float* __restrict__ wfft1, const float* __restrict__ wfft2) {
    int idx = blockIdx.x * 256 + threadIdx.x;  // 4096 total
    int t = idx >> 6, s = idx & 63;
    float acc = 0.f;
#pragma unroll
    for (int u = 0; u < 48; u++)
        acc += wfft2[t * 48 + u] * wfft1[u * 64 + s];
    g_M[t * 64 + s] = acc;
}

// carry rows 32..63 = x[:, 0:32, :]
__global__ void initCarry_kernel(const float* __restrict__ x) {
    int idx = blockIdx.x * 256 + threadIdx.x;  // 4*32*1024 = 131072
    int b = idx >> 15;
    int rem = idx & 32767;
    int t = rem >> 10;
    int e = rem & 1023;
    g_carry[(b * 64 + 32 + t) * E_DIM + e] = x[(b * T_TOK + t) * E_DIM + e];
}

// ---------------- LayerNorm kernels ----------------
// grid 256 (one block per row), 256 threads (4 elems each)
__global__ void ln1_kernel(const float* __restrict__ x,
                           const float* __restrict__ w, const float* __restrict__ bias,
                           int step) {
    int row = blockIdx.x;
    int b = row >> 6, t = row & 63;
    int tid = threadIdx.x;

    float4 v = make_float4(0.f, 0.f, 0.f, 0.f);
    if (t < 32) {
        v = *(const float4*)(g_carry + (b * 64 + t + 32) * E_DIM + tid * 4);
    } else {
        int gt = step * 32 + t;
        if (gt < T_TOK)
            v = *(const float4*)(x + ((size_t)b * T_TOK + gt) * E_DIM + tid * 4);
    }
    float s = v.x + v.y + v.z + v.w;
    float q = v.x * v.x + v.y * v.y + v.z * v.z + v.w * v.w;
#pragma unroll
    for (int o = 16; o > 0; o >>= 1) {
        s += __shfl_xor_sync(0xffffffffu, s, o);
        q += __shfl_xor_sync(0xffffffffu, q, o);
    }
    __shared__ float sh[2][8];
    int wi = tid >> 5, l = tid & 31;
    if (l == 0) { sh[0][wi] = s; sh[1][wi] = q; }
    __syncthreads();
    if (wi == 0) {
        s = (l < 8) ? sh[0][l] : 0.f;
        q = (l < 8) ? sh[1][l] : 0.f;
#pragma unroll
        for (int o = 4; o > 0; o >>= 1) {
            s += __shfl_xor_sync(0xffffffffu, s, o);
            q += __shfl_xor_sync(0xffffffffu, q, o);
        }
        if (l == 0) { sh[0][0] = s; sh[1][0] = q; }
    }
    __syncthreads();
    s = sh[0][0]; q = sh[1][0];
    float mu = s * (1.f / E_DIM);
    float var = q * (1.f / E_DIM) - mu * mu;
    float inv = rsqrtf(var + 1e-5f);
    float4 wv = ((const float4*)w)[tid];
    float4 bv = ((const float4*)bias)[tid];
    float4 o;
    o.x = (v.x - mu) * inv * wv.x + bv.x;
    o.y = (v.y - mu) * inv * wv.y + bv.y;
    o.z = (v.z - mu) * inv * wv.z + bv.z;
    o.w = (v.w - mu) * inv * wv.w + bv.w;
    *(float4*)(g_cn + row * E_DIM + tid * 4) = o;
}

__global__ void ln2_kernel(const float* __restrict__ w, const float* __restrict__ bias) {
    int row = blockIdx.x;
    int tid = threadIdx.x;
    float4 v = *(const float4*)(g_res2 + row * E_DIM + tid * 4);
    float s = v.x + v.y + v.z + v.w;
    float q = v.x * v.x + v.y * v.y + v.z * v.z + v.w * v.w;
#pragma unroll
    for (int o = 16; o > 0; o >>= 1) {
        s += __shfl_xor_sync(0xffffffffu, s, o);
        q += __shfl_xor_sync(0xffffffffu, q, o);
    }
    __shared__ float sh[2][8];
    int wi = tid >> 5, l = tid & 31;
    if (l == 0) { sh[0][wi] = s; sh[1][wi] = q; }
    __syncthreads();
    if (wi == 0) {
        s = (l < 8) ? sh[0][l] : 0.f;
        q = (l < 8) ? sh[1][l] : 0.f;
#pragma unroll
        for (int o = 4; o > 0; o >>= 1) {
            s += __shfl_xor_sync(0xffffffffu, s, o);
            q += __shfl_xor_sync(0xffffffffu, q, o);
        }
        if (l == 0) { sh[0][0] = s; sh[1][0] = q; }
    }
    __syncthreads();
    s = sh[0][0]; q = sh[1][0];
    float mu = s * (1.f / E_DIM);
    float var = q * (1.f / E_DIM) - mu * mu;
    float inv = rsqrtf(var + 1e-5f);
    float4 wv = ((const float4*)w)[tid];
    float4 bv = ((const float4*)bias)[tid];
    float4 o;
    o.x = (v.x - mu) * inv * wv.x + bv.x;
    o.y = (v.y - mu) * inv * wv.y + bv.y;
    o.z = (v.z - mu) * inv * wv.z + bv.z;
    o.w = (v.w - mu) * inv * wv.w + bv.w;
    *(float4*)(g_cn2 + row * E_DIM + tid * 4) = o;
}

// ---------------- fft (token mixing) + residual: res2 = M @ cn + chunk ----------------
// grid (8 e-tiles of 128, 4 batches), 256 threads: tx = e-in-tile, ty = t-half
__global__ __launch_bounds__(256) void fft_kernel(const float* __restrict__ x, int step) {
    __shared__ float sM[64 * 64];
    int b = blockIdx.y, bx = blockIdx.x;
    int tid = threadIdx.x;
    for (int i = tid; i < 4096; i += 256) sM[i] = g_M[i];
    __syncthreads();

    int tx = tid & 127, ty = tid >> 7;
    int e = bx * 128 + tx;
    float acc[32];
#pragma unroll
    for (int i = 0; i < 32; i++) acc[i] = 0.f;

    const float* cnb = g_cn + b * 64 * E_DIM + e;
    const float4* mbase = ((const float4*)sM) + (ty * 32) * 16;
#pragma unroll 4
    for (int s = 0; s < 64; s += 4) {
        float v0 = cnb[(s + 0) * E_DIM];
        float v1 = cnb[(s + 1) * E_DIM];
        float v2 = cnb[(s + 2) * E_DIM];
        float v3 = cnb[(s + 3) * E_DIM];
        const float4* mrow = mbase + (s >> 2);
#pragma unroll
        for (int tt = 0; tt < 32; tt++) {
            float4 m = mrow[tt * 16];
            acc[tt] += m.x * v0 + m.y * v1 + m.z * v2 + m.w * v3;
        }
    }
#pragma unroll
    for (int tt = 0; tt < 32; tt++) {
        int t = ty * 32 + tt;
        int gt = step * 32 + t;
        float xv = 0.f;
        if (gt < T_TOK) xv = x[((size_t)b * T_TOK + gt) * E_DIM + e];
        g_res2[(b * 64 + t) * E_DIM + e] = acc[tt] + xv;
    }
}

// ---------------- up GEMM + sin gating (TF32 mma.sync) ----------------
// C = cn2(256x1024) @ w_up^T ; f = sin(gate+b)*(val+b)
// grid (64 n-tiles of 64 gate cols, 2 m-tiles of 128); 256 threads, 8 warps (2m x 4n)
// Unified B tile of 128 rows: per warp_n, rows [wn*32, wn*32+16) = gate cols,
// [wn*32+16, wn*32+32) = matching val cols --> pairing is intra-thread.
__global__ __launch_bounds__(256) void up_kernel(const float* __restrict__ Wup,
                                                 const float* __restrict__ bup) {
    __shared__ uint32_t As[128][20];
    __shared__ uint32_t Bs[128][20];
    const int bx = blockIdx.x, by = blockIdx.y;
    const int tid = threadIdx.x;
    const int warp = tid >> 5, lane = tid & 31, grp = lane >> 2, tig = lane & 3;
    const int wm = warp >> 2, wn = warp & 3;

    float4 acc[4][4];
#pragma unroll
    for (int i = 0; i < 4; i++)
#pragma unroll
        for (int j = 0; j < 4; j++) acc[i][j] = make_float4(0.f, 0.f, 0.f, 0.f);

    for (int k0 = 0; k0 < E_DIM; k0 += 16) {
#pragma unroll
        for (int it = 0; it < 2; it++) {
            int l = tid + it * 256;   // 0..511
            int r = l >> 2, c = (l & 3) * 4;
            float4 v = *(const float4*)(g_cn2 + (by * 128 + r) * E_DIM + k0 + c);
            As[r][c] = f2tf(v.x); As[r][c + 1] = f2tf(v.y);
            As[r][c + 2] = f2tf(v.z); As[r][c + 3] = f2tf(v.w);
            int wn_ = r >> 5, rr = r & 31;
            int wrow = (rr < 16) ? (bx * 64 + wn_ * 16 + rr)
                                 : (DFF + bx * 64 + wn_ * 16 + (rr - 16));
            float4 w4 = *(const float4*)(Wup + (size_t)wrow * E_DIM + k0 + c);
            Bs[r][c] = f2tf(w4.x); Bs[r][c + 1] = f2tf(w4.y);
            Bs[r][c + 2] = f2tf(w4.z); Bs[r][c + 3] = f2tf(w4.w);
        }
        __syncthreads();
#pragma unroll
        for (int kk = 0; kk < 16; kk += 8) {
            uint32_t af[4][4], bfr[4][2];
#pragma unroll
            for (int tm = 0; tm < 4; tm++) {
                int ra = wm * 64 + tm * 16 + grp;
                af[tm][0] = As[ra][kk + tig];
                af[tm][1] = As[ra + 8][kk + tig];
                af[tm][2] = As[ra][kk + tig + 4];
                af[tm][3] = As[ra + 8][kk + tig + 4];
            }
#pragma unroll
            for (int tn = 0; tn < 4; tn++) {
                int rb = wn * 32 + tn * 8 + grp;
                bfr[tn][0] = Bs[rb][kk + tig];
                bfr[tn][1] = Bs[rb][kk + tig + 4];
            }
#pragma unroll
            for (int tm = 0; tm < 4; tm++)
#pragma unroll
                for (int tn = 0; tn < 4; tn++)
                    mma8(acc[tm][tn], af[tm], bfr[tn]);
        }
        __syncthreads();
    }

    // epilogue: gate tile tn pairs with val tile tn+2 (same thread, same layout)
#pragma unroll
    for (int tm = 0; tm < 4; tm++) {
#pragma unroll
        for (int tn = 0; tn < 2; tn++) {
            float4 g = acc[tm][tn];
            float4 v = acc[tm][tn + 2];
            int jg = bx * 64 + wn * 16 + tn * 8 + 2 * tig;       // gate col in [0,4096)
            float bg0 = bup[jg], bg1 = bup[jg + 1];
            float bv0 = bup[DFF + jg], bv1 = bup[DFF + jg + 1];
            int m0 = by * 128 + wm * 64 + tm * 16 + grp;
            float2 lo, hi;
            lo.x = __sinf(g.x + bg0) * (v.x + bv0);
            lo.y = __sinf(g.y + bg1) * (v.y + bv1);
            hi.x = __sinf(g.z + bg0) * (v.z + bv0);
            hi.y = __sinf(g.w + bg1) * (v.w + bv1);
            *(float2*)(g_f + (size_t)m0 * DFF + jg) = lo;
            *(float2*)(g_f + (size_t)(m0 + 8) * DFF + jg) = hi;
        }
    }
}

// ---------------- down GEMM, split-K = 4 (deterministic partial buffers) ----------------
// out_part = f(256x4096 slice) @ w_down^T ; grid (16 n-tiles, 2 m-tiles, 4 k-splits)
__global__ __launch_bounds__(256) void down_kernel(const float* __restrict__ Wdn) {
    __shared__ uint32_t As[128][20];
    __shared__ uint32_t Bs[64][20];
    const int bx = blockIdx.x, by = blockIdx.y, bz = blockIdx.z;
    const int tid = threadIdx.x;
    const int warp = tid >> 5, lane = tid & 31, grp = lane >> 2, tig = lane & 3;
    const int wm = warp >> 2, wn = warp & 3;

    float4 acc[4][2];
#pragma unroll
    for (int i = 0; i < 4; i++) {
        acc[i][0] = make_float4(0.f, 0.f, 0.f, 0.f);
        acc[i][1] = make_float4(0.f, 0.f, 0.f, 0.f);
    }

    for (int k0 = 0; k0 < 1024; k0 += 16) {
#pragma unroll
        for (int it = 0; it < 2; it++) {
            int l = tid + it * 256;
            int r = l >> 2, c = (l & 3) * 4;
            float4 v = *(const float4*)(g_f + (size_t)(by * 128 + r) * DFF + bz * 1024 + k0 + c);
            As[r][c] = f2tf(v.x); As[r][c + 1] = f2tf(v.y);
            As[r][c + 2] = f2tf(v.z); As[r][c + 3] = f2tf(v.w);
        }
        {
            int u = tid >> 2, c = (tid & 3) * 4;
            int wrow = bx * 64 + u;
            float4 w4 = *(const float4*)(Wdn + (size_t)wrow * DFF + bz * 1024 + k0 + c);
            Bs[u][c] = f2tf(w4.x); Bs[u][c + 1] = f2tf(w4.y);
            Bs[u][c + 2] = f2tf(w4.z); Bs[u][c + 3] = f2tf(w4.w);
        }
        __syncthreads();
#pragma unroll
        for (int kk = 0; kk < 16; kk += 8) {
            uint32_t af[4][4], bfr[2][2];
#pragma unroll
            for (int tm = 0; tm < 4; tm++) {
                int ra = wm * 64 + tm * 16 + grp;
                af[tm][0] = As[ra][kk + tig];
                af[tm][1] = As[ra + 8][kk + tig];
                af[tm][2] = As[ra][kk + tig + 4];
                af[tm][3] = As[ra + 8][kk + tig + 4];
            }
#pragma unroll
            for (int tn = 0; tn < 2; tn++) {
                int rb = wn * 16 + tn * 8 + grp;
                bfr[tn][0] = Bs[rb][kk + tig];
                bfr[tn][1] = Bs[rb][kk + tig + 4];
            }
#pragma unroll
            for (int tm = 0; tm < 4; tm++)
#pragma unroll
                for (int tn = 0; tn < 2; tn++)
                    mma8(acc[tm][tn], af[tm], bfr[tn]);
        }
        __syncthreads();
    }

#pragma unroll
    for (int tm = 0; tm < 4; tm++) {
#pragma unroll
        for (int tn = 0; tn < 2; tn++) {
            int n = bx * 64 + wn * 16 + tn * 8 + 2 * tig;
            int m = by * 128 + wm * 64 + tm * 16 + grp;
            float4 a = acc[tm][tn];
            *(float2*)(g_part + (size_t)(bz * 256 + m) * E_DIM + n) = make_float2(a.x, a.y);
            *(float2*)(g_part + (size_t)(bz * 256 + m + 8) * E_DIM + n) = make_float2(a.z, a.w);
        }
    }
}

// ---------------- reduce: proc = sum(parts) + b_down + res2 ; write out + carry ----------------
__global__ void reduce_kernel(const float* __restrict__ bdown, float* __restrict__ dout, int step) {
    int row = blockIdx.x;   // 0..255
    int tid = threadIdx.x;
    int b = row >> 6, t = row & 63;
    size_t off = (size_t)row * E_DIM + tid * 4;

    float4 p0 = *(const float4*)(g_part + off);
    float4 p1 = *(const float4*)(g_part + 262144 + off);
    float4 p2 = *(const float4*)(g_part + 2 * 262144 + off);
    float4 p3 = *(const float4*)(g_part + 3 * 262144 + off);
    float4 bd = ((const float4*)bdown)[tid];
    float4 r2 = *(const float4*)(g_res2 + off);
    float4 v;
    v.x = p0.x + p1.x + p2.x + p3.x + bd.x + r2.x;
    v.y = p0.y + p1.y + p2.y + p3.y + bd.y + r2.y;
    v.z = p0.z + p1.z + p2.z + p3.z + bd.z + r2.z;
    v.w = p0.w + p1.w + p2.w + p3.w + bd.w + r2.w;

    *(float4*)(g_carry + off) = v;
    if (t < 32)
        *(float4*)(dout + ((size_t)b * T_TOK + step * 32 + t) * E_DIM + tid * 4) = v;
}

// ---------------- launch ----------------
extern "C" void kernel_launch(void* const* d_in, const int* in_sizes, int n_in,
                              void* d_out, int out_size) {
    const float* x     = (const float*)d_in[0];
    const float* ln1w  = (const float*)d_in[1];
    const float* ln1b  = (const float*)d_in[2];
    const float* wfft1 = (const float*)d_in[3];
    const float* wfft2 = (const float*)d_in[4];
    const float* ln2w  = (const float*)d_in[5];
    const float* ln2b  = (const float*)d_in[6];
    const float* wup   = (const float*)d_in[7];
    const float* bup   = (const float*)d_in[8];
    const float* wdn   = (const float*)d_in[9];
    const float* bdn   = (const float*)d_in[10];
    float* out = (float*)d_out;

    initM_kernel<<<16, 256>>>(wfft1, wfft2);
    initCarry_kernel<<<512, 256>>>(x);

    for (int i = 0; i < NSTEP; i++) {
        ln1_kernel<<<256, 256>>>(x, ln1w, ln1b, i);
        fft_kernel<<<dim3(8, 4), 256>>>(x, i);
        ln2_kernel<<<256, 256>>>(ln2w, ln2b);
        up_kernel<<<dim3(64, 2), 256>>>(wup, bup);
        down_kernel<<<dim3(16, 2, 4), 256>>>(wdn);
        reduce_kernel<<<256, 256>>>(bdn, out, i);
    }
}

// round 2
// speedup vs baseline: 1.6264x; 1.6264x over previous
#include <cuda_runtime.h>
#include <cstdint>

#define T_TOK 4096
#define E_DIM 1024
#define DFF   4096
#define BB    4
#define NSTEP 128
#define TPAD  (T_TOK + 32)   // 4128 padded token rows

// ---------------- device global scratch ----------------
__device__ float    g_M[64 * 64];                       // w_fft2 @ w_fft1
__device__ float    g_LNx[(size_t)BB * TPAD * E_DIM];   // LN1(x) for every token slot (+pad)
__device__ float    g_cnlo[BB * 32 * E_DIM];            // LN1(prev proc rows 32..63)
__device__ float    g_res2[BB * 64 * E_DIM];            // fft + chunk
__device__ uint32_t g_cn2t[BB * 64 * E_DIM];            // LN2 output, tf32 bits
__device__ uint32_t g_ft[(size_t)BB * 64 * DFF];        // sin(gate)*val, tf32 bits
__device__ float    g_part[4 * BB * 64 * E_DIM];        // split-K partials
__device__ uint32_t g_wupt[(size_t)2 * DFF * E_DIM];    // w_up in tf32
__device__ uint32_t g_wdnt[(size_t)E_DIM * DFF];        // w_down in tf32

// ---------------- helpers ----------------
__device__ __forceinline__ uint32_t f2tf(float f) {
    uint32_t r;
    asm("cvt.rna.tf32.f32 %0, %1;" : "=r"(r) : "f"(f));
    return r;
}
__device__ __forceinline__ void mma8(float4& d, const uint32_t* a, const uint32_t* b) {
    asm volatile(
        "mma.sync.aligned.m16n8k8.row.col.f32.tf32.tf32.f32 "
        "{%0,%1,%2,%3},{%4,%5,%6,%7},{%8,%9},{%0,%1,%2,%3};\n"
        : "+f"(d.x), "+f"(d.y), "+f"(d.z), "+f"(d.w)
        : "r"(a[0]), "r"(a[1]), "r"(a[2]), "r"(a[3]), "r"(b[0]), "r"(b[1]));
}
__device__ __forceinline__ uint32_t smem_u32(const void* p) {
    return (uint32_t)__cvta_generic_to_shared(p);
}
#define CP16(dst, src) asm volatile("cp.async.cg.shared.global [%0],[%1],16;\n" :: "r"(dst), "l"(src))
#define CPCOMMIT()     asm volatile("cp.async.commit_group;\n")
#define CPWAIT1()      asm volatile("cp.async.wait_group 1;\n")
#define CPWAIT0()      asm volatile("cp.async.wait_group 0;\n")

// ---------------- init: M = w_fft2 @ w_fft1 ----------------
__global__ void initM_kernel(const float* __restrict__ wfft1, const float* __restrict__ wfft2) {
    int idx = blockIdx.x * 256 + threadIdx.x;  // 4096
    int t = idx >> 6, s = idx & 63;
    float acc = 0.f;
#pragma unroll
    for (int u = 0; u < 48; u++)
        acc += wfft2[t * 48 + u] * wfft1[u * 64 + s];
    g_M[t * 64 + s] = acc;
}

// ---------------- init: weight conversion to tf32 ----------------
__global__ void cvt_up_kernel(const float* __restrict__ w) {
    size_t i = ((size_t)blockIdx.x * 256 + threadIdx.x) * 4;
    float4 v = *(const float4*)(w + i);
    uint4 o = make_uint4(f2tf(v.x), f2tf(v.y), f2tf(v.z), f2tf(v.w));
    *(uint4*)(g_wupt + i) = o;
}
__global__ void cvt_dn_kernel(const float* __restrict__ w) {
    size_t i = ((size_t)blockIdx.x * 256 + threadIdx.x) * 4;
    float4 v = *(const float4*)(w + i);
    uint4 o = make_uint4(f2tf(v.x), f2tf(v.y), f2tf(v.z), f2tf(v.w));
    *(uint4*)(g_wdnt + i) = o;
}

// ---------------- init: LN1(x) for all token slots (incl. zero pad) ----------------
__global__ void lnx_kernel(const float* __restrict__ x,
                           const float* __restrict__ w, const float* __restrict__ bias) {
    int row = blockIdx.x;              // 0 .. BB*TPAD-1
    int b = row / TPAD, j = row % TPAD;
    int tid = threadIdx.x;

    float4 v = make_float4(0.f, 0.f, 0.f, 0.f);
    if (j < T_TOK) v = *(const float4*)(x + ((size_t)b * T_TOK + j) * E_DIM + tid * 4);

    float s = v.x + v.y + v.z + v.w;
    float q = v.x * v.x + v.y * v.y + v.z * v.z + v.w * v.w;
#pragma unroll
    for (int o = 16; o > 0; o >>= 1) {
        s += __shfl_xor_sync(0xffffffffu, s, o);
        q += __shfl_xor_sync(0xffffffffu, q, o);
    }
    __shared__ float sh[2][8];
    int wi = tid >> 5, l = tid & 31;
    if (l == 0) { sh[0][wi] = s; sh[1][wi] = q; }
    __syncthreads();
    if (wi == 0) {
        s = (l < 8) ? sh[0][l] : 0.f;
        q = (l < 8) ? sh[1][l] : 0.f;
#pragma unroll
        for (int o = 4; o > 0; o >>= 1) {
            s += __shfl_xor_sync(0xffffffffu, s, o);
            q += __shfl_xor_sync(0xffffffffu, q, o);
        }
        if (l == 0) { sh[0][0] = s; sh[1][0] = q; }
    }
    __syncthreads();
    s = sh[0][0]; q = sh[1][0];
    float mu = s * (1.f / E_DIM);
    float var = q * (1.f / E_DIM) - mu * mu;
    float inv = rsqrtf(var + 1e-5f);
    float4 wv = ((const float4*)w)[tid];
    float4 bv = ((const float4*)bias)[tid];
    float4 o;
    o.x = (v.x - mu) * inv * wv.x + bv.x;
    o.y = (v.y - mu) * inv * wv.y + bv.y;
    o.z = (v.z - mu) * inv * wv.z + bv.z;
    o.w = (v.w - mu) * inv * wv.w + bv.w;
    *(float4*)(g_LNx + ((size_t)b * TPAD + j) * E_DIM + tid * 4) = o;
    if (j < 32)
        *(float4*)(g_cnlo + ((size_t)b * 32 + j) * E_DIM + tid * 4) = o;
}

// ---------------- fft: res2 = M @ cn + chunk ----------------
// grid (8 e-blocks, 4 t-quarters, BB), 256 threads = 128 e-lanes x 2 t-halves(8 rows)
__global__ __launch_bounds__(256) void fft_kernel(const float* __restrict__ x, int step) {
    int eb = blockIdx.x, tq = blockIdx.y, b = blockIdx.z;
    int tid = threadIdx.x;
    int el = tid & 127, th = tid >> 7;
    int e = eb * 128 + el;

    __shared__ float sMt[16 * 64];
    for (int i = tid; i < 1024; i += 256) {
        int tt = i >> 6, s = i & 63;
        sMt[i] = g_M[(tq * 16 + tt) * 64 + s];
    }
    __syncthreads();

    float acc[8];
#pragma unroll
    for (int i = 0; i < 8; i++) acc[i] = 0.f;

    const float* cnlo = g_cnlo + (size_t)b * 32 * E_DIM + e;
    const float* lnxb = g_LNx + ((size_t)b * TPAD + step * 32) * E_DIM + e;
    const float* mrow = sMt + th * 8 * 64;

#pragma unroll 4
    for (int s = 0; s < 32; s++) {
        float v = cnlo[(size_t)s * E_DIM];
#pragma unroll
        for (int tt = 0; tt < 8; tt++) acc[tt] += mrow[tt * 64 + s] * v;
    }
#pragma unroll 4
    for (int s = 32; s < 64; s++) {
        float v = lnxb[(size_t)s * E_DIM];
#pragma unroll
        for (int tt = 0; tt < 8; tt++) acc[tt] += mrow[tt * 64 + s] * v;
    }

#pragma unroll
    for (int tt = 0; tt < 8; tt++) {
        int t = tq * 16 + th * 8 + tt;
        int gt = step * 32 + t;
        float xv = (gt < T_TOK) ? x[((size_t)b * T_TOK + gt) * E_DIM + e] : 0.f;
        g_res2[((size_t)(b * 64 + t)) * E_DIM + e] = acc[tt] + xv;
    }
}

// ---------------- LN2: cn2t = tf32(LN(res2)) ----------------
__global__ void ln2_kernel(const float* __restrict__ w, const float* __restrict__ bias) {
    int row = blockIdx.x;
    int tid = threadIdx.x;
    float4 v = *(const float4*)(g_res2 + (size_t)row * E_DIM + tid * 4);
    float s = v.x + v.y + v.z + v.w;
    float q = v.x * v.x + v.y * v.y + v.z * v.z + v.w * v.w;
#pragma unroll
    for (int o = 16; o > 0; o >>= 1) {
        s += __shfl_xor_sync(0xffffffffu, s, o);
        q += __shfl_xor_sync(0xffffffffu, q, o);
    }
    __shared__ float sh[2][8];
    int wi = tid >> 5, l = tid & 31;
    if (l == 0) { sh[0][wi] = s; sh[1][wi] = q; }
    __syncthreads();
    if (wi == 0) {
        s = (l < 8) ? sh[0][l] : 0.f;
        q = (l < 8) ? sh[1][l] : 0.f;
#pragma unroll
        for (int o = 4; o > 0; o >>= 1) {
            s += __shfl_xor_sync(0xffffffffu, s, o);
            q += __shfl_xor_sync(0xffffffffu, q, o);
        }
        if (l == 0) { sh[0][0] = s; sh[1][0] = q; }
    }
    __syncthreads();
    s = sh[0][0]; q = sh[1][0];
    float mu = s * (1.f / E_DIM);
    float var = q * (1.f / E_DIM) - mu * mu;
    float inv = rsqrtf(var + 1e-5f);
    float4 wv = ((const float4*)w)[tid];
    float4 bv = ((const float4*)bias)[tid];
    uint4 o;
    o.x = f2tf((v.x - mu) * inv * wv.x + bv.x);
    o.y = f2tf((v.y - mu) * inv * wv.y + bv.y);
    o.z = f2tf((v.z - mu) * inv * wv.z + bv.z);
    o.w = f2tf((v.w - mu) * inv * wv.w + bv.w);
    *(uint4*)(g_cn2t + (size_t)row * E_DIM + tid * 4) = o;
}

// ---------------- up GEMM + sin gating (3-stage cp.async, tf32 mma) ----------------
// grid (64 gate-tiles of 64 cols, 2 m-tiles of 128); 256 threads = 8 warps (2m x 4n)
#define UP_SLOT_W 5120          // words per stage (A 2560 + B 2560)
__global__ __launch_bounds__(256) void up_kernel(const float* __restrict__ bup) {
    extern __shared__ uint32_t sm[];
    const int bx = blockIdx.x, by = blockIdx.y;
    const int tid = threadIdx.x;
    const int warp = tid >> 5, lane = tid & 31, grp = lane >> 2, tig = lane & 3;
    const int wm = warp >> 2, wn = warp & 3;

    const int r0 = tid >> 2, c0 = (tid & 3) * 4;
    const int r1 = r0 + 64;

    const uint32_t* gA0 = g_cn2t + (size_t)(by * 128 + r0) * E_DIM + c0;
    const uint32_t* gA1 = g_cn2t + (size_t)(by * 128 + r1) * E_DIM + c0;
    int wn0 = r0 >> 5, rr0 = r0 & 31;
    int wrow0 = (rr0 < 16) ? (bx * 64 + wn0 * 16 + rr0) : (DFF + bx * 64 + wn0 * 16 + (rr0 - 16));
    int wn1 = r1 >> 5, rr1 = r1 & 31;
    int wrow1 = (rr1 < 16) ? (bx * 64 + wn1 * 16 + rr1) : (DFF + bx * 64 + wn1 * 16 + (rr1 - 16));
    const uint32_t* gB0 = g_wupt + (size_t)wrow0 * E_DIM + c0;
    const uint32_t* gB1 = g_wupt + (size_t)wrow1 * E_DIM + c0;

    const uint32_t sbase = smem_u32(sm);
    const uint32_t dA0 = sbase + (r0 * 20 + c0) * 4;
    const uint32_t dA1 = sbase + (r1 * 20 + c0) * 4;
    const uint32_t dB0 = sbase + (2560 + r0 * 20 + c0) * 4;
    const uint32_t dB1 = sbase + (2560 + r1 * 20 + c0) * 4;
    const uint32_t slotB = UP_SLOT_W * 4;

    float4 acc[4][4];
#pragma unroll
    for (int i = 0; i < 4; i++)
#pragma unroll
        for (int j = 0; j < 4; j++) acc[i][j] = make_float4(0.f, 0.f, 0.f, 0.f);

    // prologue: chunks 0,1 -> slots 0,1
    CP16(dA0, gA0); CP16(dA1, gA1); CP16(dB0, gB0); CP16(dB1, gB1); CPCOMMIT();
    CP16(dA0 + slotB, gA0 + 16); CP16(dA1 + slotB, gA1 + 16);
    CP16(dB0 + slotB, gB0 + 16); CP16(dB1 + slotB, gB1 + 16); CPCOMMIT();

    for (int k = 0; k < 64; k++) {
        if (k < 63) CPWAIT1(); else CPWAIT0();
        __syncthreads();
        if (k + 2 < 64) {
            int slot = (k + 2) % 3;
            uint32_t so = slot * slotB;
            int off = (k + 2) * 16;
            CP16(dA0 + so, gA0 + off); CP16(dA1 + so, gA1 + off);
            CP16(dB0 + so, gB0 + off); CP16(dB1 + so, gB1 + off);
            CPCOMMIT();
        }
        const uint32_t* As = sm + (k % 3) * UP_SLOT_W;
        const uint32_t* Bs = As + 2560;
#pragma unroll
        for (int kk = 0; kk < 16; kk += 8) {
            uint32_t af[4][4], bf[4][2];
#pragma unroll
            for (int tm = 0; tm < 4; tm++) {
                int ra = wm * 64 + tm * 16 + grp;
                af[tm][0] = As[ra * 20 + kk + tig];
                af[tm][1] = As[(ra + 8) * 20 + kk + tig];
                af[tm][2] = As[ra * 20 + kk + tig + 4];
                af[tm][3] = As[(ra + 8) * 20 + kk + tig + 4];
            }
#pragma unroll
            for (int tn = 0; tn < 4; tn++) {
                int rb = wn * 32 + tn * 8 + grp;
                bf[tn][0] = Bs[rb * 20 + kk + tig];
                bf[tn][1] = Bs[rb * 20 + kk + tig + 4];
            }
#pragma unroll
            for (int tm = 0; tm < 4; tm++)
#pragma unroll
                for (int tn = 0; tn < 4; tn++)
                    mma8(acc[tm][tn], af[tm], bf[tn]);
        }
    }

    // epilogue: gate tile tn pairs with val tile tn+2
#pragma unroll
    for (int tm = 0; tm < 4; tm++) {
#pragma unroll
        for (int tn = 0; tn < 2; tn++) {
            float4 g = acc[tm][tn];
            float4 v = acc[tm][tn + 2];
            int jg = bx * 64 + wn * 16 + tn * 8 + 2 * tig;
            float bg0 = bup[jg], bg1 = bup[jg + 1];
            float bv0 = bup[DFF + jg], bv1 = bup[DFF + jg + 1];
            int m0 = by * 128 + wm * 64 + tm * 16 + grp;
            uint2 lo, hi;
            lo.x = f2tf(__sinf(g.x + bg0) * (v.x + bv0));
            lo.y = f2tf(__sinf(g.y + bg1) * (v.y + bv1));
            hi.x = f2tf(__sinf(g.z + bg0) * (v.z + bv0));
            hi.y = f2tf(__sinf(g.w + bg1) * (v.w + bv1));
            *(uint2*)(g_ft + (size_t)m0 * DFF + jg) = lo;
            *(uint2*)(g_ft + (size_t)(m0 + 8) * DFF + jg) = hi;
        }
    }
}

// ---------------- down GEMM, split-K=4 (3-stage cp.async) ----------------
#define DN_SLOT_W 3840          // A 2560 + B 1280
__global__ __launch_bounds__(256) void down_kernel() {
    extern __shared__ uint32_t sm[];
    const int bx = blockIdx.x, by = blockIdx.y, bz = blockIdx.z;
    const int tid = threadIdx.x;
    const int warp = tid >> 5, lane = tid & 31, grp = lane >> 2, tig = lane & 3;
    const int wm = warp >> 2, wn = warp & 3;

    const int r0 = tid >> 2, c0 = (tid & 3) * 4;
    const int r1 = r0 + 64;

    const uint32_t* gA0 = g_ft + (size_t)(by * 128 + r0) * DFF + bz * 1024 + c0;
    const uint32_t* gA1 = g_ft + (size_t)(by * 128 + r1) * DFF + bz * 1024 + c0;
    const uint32_t* gB0 = g_wdnt + (size_t)(bx * 64 + r0) * DFF + bz * 1024 + c0;

    const uint32_t sbase = smem_u32(sm);
    const uint32_t dA0 = sbase + (r0 * 20 + c0) * 4;
    const uint32_t dA1 = sbase + (r1 * 20 + c0) * 4;
    const uint32_t dB0 = sbase + (2560 + r0 * 20 + c0) * 4;   // r0 < 64 rows used
    const uint32_t slotB = DN_SLOT_W * 4;

    float4 acc[4][2];
#pragma unroll
    for (int i = 0; i < 4; i++) {
        acc[i][0] = make_float4(0.f, 0.f, 0.f, 0.f);
        acc[i][1] = make_float4(0.f, 0.f, 0.f, 0.f);
    }

    // B: only threads with r0<64 load (256 threads cover 64 rows x 4 segs exactly: tid>>2 in 0..63) -> all threads load B once
    CP16(dA0, gA0); CP16(dA1, gA1); CP16(dB0, gB0); CPCOMMIT();
    CP16(dA0 + slotB, gA0 + 16); CP16(dA1 + slotB, gA1 + 16); CP16(dB0 + slotB, gB0 + 16); CPCOMMIT();

    for (int k = 0; k < 64; k++) {
        if (k < 63) CPWAIT1(); else CPWAIT0();
        __syncthreads();
        if (k + 2 < 64) {
            int slot = (k + 2) % 3;
            uint32_t so = slot * slotB;
            int off = (k + 2) * 16;
            CP16(dA0 + so, gA0 + off); CP16(dA1 + so, gA1 + off); CP16(dB0 + so, gB0 + off);
            CPCOMMIT();
        }
        const uint32_t* As = sm + (k % 3) * DN_SLOT_W;
        const uint32_t* Bs = As + 2560;
#pragma unroll
        for (int kk = 0; kk < 16; kk += 8) {
            uint32_t af[4][4], bf[2][2];
#pragma unroll
            for (int tm = 0; tm < 4; tm++) {
                int ra = wm * 64 + tm * 16 + grp;
                af[tm][0] = As[ra * 20 + kk + tig];
                af[tm][1] = As[(ra + 8) * 20 + kk + tig];
                af[tm][2] = As[ra * 20 + kk + tig + 4];
                af[tm][3] = As[(ra + 8) * 20 + kk + tig + 4];
            }
#pragma unroll
            for (int tn = 0; tn < 2; tn++) {
                int rb = wn * 16 + tn * 8 + grp;
                bf[tn][0] = Bs[rb * 20 + kk + tig];
                bf[tn][1] = Bs[rb * 20 + kk + tig + 4];
            }
#pragma unroll
            for (int tm = 0; tm < 4; tm++)
#pragma unroll
                for (int tn = 0; tn < 2; tn++)
                    mma8(acc[tm][tn], af[tm], bf[tn]);
        }
    }

#pragma unroll
    for (int tm = 0; tm < 4; tm++) {
#pragma unroll
        for (int tn = 0; tn < 2; tn++) {
            int n = bx * 64 + wn * 16 + tn * 8 + 2 * tig;
            int m = by * 128 + wm * 64 + tm * 16 + grp;
            float4 a = acc[tm][tn];
            *(float2*)(g_part + (size_t)(bz * 256 + m) * E_DIM + n) = make_float2(a.x, a.y);
            *(float2*)(g_part + (size_t)(bz * 256 + m + 8) * E_DIM + n) = make_float2(a.z, a.w);
        }
    }
}

// ---------------- reduce + fused LN1 of carry rows ----------------
__global__ void reduce_kernel(const float* __restrict__ ln1w, const float* __restrict__ ln1b,
                              const float* __restrict__ bdown, float* __restrict__ dout, int step) {
    int row = blockIdx.x;   // 0..255
    int tid = threadIdx.x;
    int b = row >> 6, t = row & 63;
    size_t off = (size_t)row * E_DIM + tid * 4;

    float4 p0 = *(const float4*)(g_part + off);
    float4 p1 = *(const float4*)(g_part + 262144 + off);
    float4 p2 = *(const float4*)(g_part + 2 * 262144 + off);
    float4 p3 = *(const float4*)(g_part + 3 * 262144 + off);
    float4 bd = ((const float4*)bdown)[tid];
    float4 r2 = *(const float4*)(g_res2 + off);
    float4 v;
    v.x = p0.x + p1.x + p2.x + p3.x + bd.x + r2.x;
    v.y = p0.y + p1.y + p2.y + p3.y + bd.y + r2.y;
    v.z = p0.z + p1.z + p2.z + p3.z + bd.z + r2.z;
    v.w = p0.w + p1.w + p2.w + p3.w + bd.w + r2.w;

    if (t < 32) {
        *(float4*)(dout + ((size_t)b * T_TOK + step * 32 + t) * E_DIM + tid * 4) = v;
        return;   // block-uniform
    }

    // LN1 on carry rows 32..63 -> g_cnlo for next step
    float s = v.x + v.y + v.z + v.w;
    float q = v.x * v.x + v.y * v.y + v.z * v.z + v.w * v.w;
#pragma unroll
    for (int o = 16; o > 0; o >>= 1) {
        s += __shfl_xor_sync(0xffffffffu, s, o);
        q += __shfl_xor_sync(0xffffffffu, q, o);
    }
    __shared__ float sh[2][8];
    int wi = tid >> 5, l = tid & 31;
    if (l == 0) { sh[0][wi] = s; sh[1][wi] = q; }
    __syncthreads();
    if (wi == 0) {
        s = (l < 8) ? sh[0][l] : 0.f;
        q = (l < 8) ? sh[1][l] : 0.f;
#pragma unroll
        for (int o = 4; o > 0; o >>= 1) {
            s += __shfl_xor_sync(0xffffffffu, s, o);
            q += __shfl_xor_sync(0xffffffffu, q, o);
        }
        if (l == 0) { sh[0][0] = s; sh[1][0] = q; }
    }
    __syncthreads();
    s = sh[0][0]; q = sh[1][0];
    float mu = s * (1.f / E_DIM);
    float var = q * (1.f / E_DIM) - mu * mu;
    float inv = rsqrtf(var + 1e-5f);
    float4 wv = ((const float4*)ln1w)[tid];
    float4 bv = ((const float4*)ln1b)[tid];
    float4 o;
    o.x = (v.x - mu) * inv * wv.x + bv.x;
    o.y = (v.y - mu) * inv * wv.y + bv.y;
    o.z = (v.z - mu) * inv * wv.z + bv.z;
    o.w = (v.w - mu) * inv * wv.w + bv.w;
    *(float4*)(g_cnlo + ((size_t)(b * 32 + (t - 32))) * E_DIM + tid * 4) = o;
}

// ---------------- launch ----------------
extern "C" void kernel_launch(void* const* d_in, const int* in_sizes, int n_in,
                              void* d_out, int out_size) {
    const float* x     = (const float*)d_in[0];
    const float* ln1w  = (const float*)d_in[1];
    const float* ln1b  = (const float*)d_in[2];
    const float* wfft1 = (const float*)d_in[3];
    const float* wfft2 = (const float*)d_in[4];
    const float* ln2w  = (const float*)d_in[5];
    const float* ln2b  = (const float*)d_in[6];
    const float* wup   = (const float*)d_in[7];
    const float* bup   = (const float*)d_in[8];
    const float* wdn   = (const float*)d_in[9];
    const float* bdn   = (const float*)d_in[10];
    float* out = (float*)d_out;

    cudaFuncSetAttribute(up_kernel, cudaFuncAttributeMaxDynamicSharedMemorySize, UP_SLOT_W * 3 * 4);
    cudaFuncSetAttribute(down_kernel, cudaFuncAttributeMaxDynamicSharedMemorySize, DN_SLOT_W * 3 * 4);

    initM_kernel<<<16, 256>>>(wfft1, wfft2);
    cvt_up_kernel<<<8192, 256>>>(wup);
    cvt_dn_kernel<<<4096, 256>>>(wdn);
    lnx_kernel<<<BB * TPAD, 256>>>(x, ln1w, ln1b);

    for (int i = 0; i < NSTEP; i++) {
        fft_kernel<<<dim3(8, 4, BB), 256>>>(x, i);
        ln2_kernel<<<256, 256>>>(ln2w, ln2b);
        up_kernel<<<dim3(64, 2), 256, UP_SLOT_W * 3 * 4>>>(bup);
        down_kernel<<<dim3(16, 2, 4), 256, DN_SLOT_W * 3 * 4>>>();
        reduce_kernel<<<256, 256>>>(ln1w, ln1b, bdn, out, i);
    }
}